// round 3
// baseline (speedup 1.0000x reference)
#include <cuda_runtime.h>
#include <cstdint>
typedef unsigned long long ull;

__device__ float g_xp[(size_t)1024 * 512 * 512];  // 1 GiB gate preacts
__device__ float g_h1[(size_t)1024 * 512 * 128];  // 256 MB layer-0 h seq
__device__ float g_h2[1024 * 128];

__device__ __forceinline__ ull pk2(float a, float b) { ull r; asm("mov.b64 %0,{%1,%2};" : "=l"(r) : "f"(a), "f"(b)); return r; }
__device__ __forceinline__ void upk2(ull p, float& a, float& b) { asm("mov.b64 {%0,%1},%2;" : "=f"(a), "=f"(b) : "l"(p)); }
__device__ __forceinline__ void fma2(ull& d, ull a, ull b) { asm("fma.rn.f32x2 %0,%1,%2,%0;" : "+l"(d) : "l"(a), "l"(b)); }
__device__ __forceinline__ float ex2f_(float x) { float r; asm("ex2.approx.f32 %0,%1;" : "=f"(r) : "f"(x)); return r; }
__device__ __forceinline__ float rcpf_(float x) { float r; asm("rcp.approx.f32 %0,%1;" : "=f"(r) : "f"(x)); return r; }
__device__ __forceinline__ float sigf(float x) { return rcpf_(1.f + ex2f_(-1.44269504f * x)); }
__device__ __forceinline__ float tanhf_(float x) { return fmaf(2.f, rcpf_(1.f + ex2f_(-2.88539009f * x)), -1.f); }

// ---- x-projection GEMM: out[row*512 + u*4 + q] = in[row] . W[q*128+u] + b ----
template <int K>
__global__ void __launch_bounds__(256)
k_xproj(const float* __restrict__ in, const float* __restrict__ W,
        const float* __restrict__ bi, const float* __restrict__ bh,
        float* __restrict__ outp)
{
    extern __shared__ float sm[];
    float* in_s = sm;             // [K][68]
    float* w_s = sm + K * 68;     // [K][132]
    const int tid = threadIdx.x, row0 = blockIdx.x * 64, gt = blockIdx.y;

    for (int i = tid; i < 64 * K; i += 256) {
        int r = i / K, k = i % K;
        in_s[k * 68 + r] = in[(size_t)(row0 + r) * K + k];
    }
    for (int i = tid; i < 128 * K; i += 256) {
        int j = i / K, k = i % K;
        int g = (j & 3) * 128 + gt * 32 + (j >> 2);
        w_s[k * 132 + j] = W[(size_t)g * K + k];
    }
    __syncthreads();

    const int gg = tid & 15, rg = tid >> 4;
    ull acc[4][4];
#pragma unroll
    for (int r = 0; r < 4; r++)
#pragma unroll
        for (int p = 0; p < 4; p++) acc[r][p] = 0ULL;

    const ulonglong2* wv = (const ulonglong2*)w_s;
    const float4* is4 = (const float4*)in_s;
#pragma unroll 4
    for (int k = 0; k < K; ++k) {
        ulonglong2 wA = wv[k * 33 + gg * 2];
        ulonglong2 wB = wv[k * 33 + gg * 2 + 1];
        float4 av = is4[k * 17 + rg];
        ull a0 = pk2(av.x, av.x), a1 = pk2(av.y, av.y);
        ull a2 = pk2(av.z, av.z), a3 = pk2(av.w, av.w);
        fma2(acc[0][0], wA.x, a0); fma2(acc[0][1], wA.y, a0); fma2(acc[0][2], wB.x, a0); fma2(acc[0][3], wB.y, a0);
        fma2(acc[1][0], wA.x, a1); fma2(acc[1][1], wA.y, a1); fma2(acc[1][2], wB.x, a1); fma2(acc[1][3], wB.y, a1);
        fma2(acc[2][0], wA.x, a2); fma2(acc[2][1], wA.y, a2); fma2(acc[2][2], wB.x, a2); fma2(acc[2][3], wB.y, a2);
        fma2(acc[3][0], wA.x, a3); fma2(acc[3][1], wA.y, a3); fma2(acc[3][2], wB.x, a3); fma2(acc[3][3], wB.y, a3);
    }

    const int j0 = gg * 8;
    float bs[8];
#pragma unroll
    for (int jj = 0; jj < 8; jj++) {
        int j = j0 + jj, g = (j & 3) * 128 + gt * 32 + (j >> 2);
        bs[jj] = bi[g] + bh[g];
    }
#pragma unroll
    for (int r = 0; r < 4; r++) {
        float v[8];
        upk2(acc[r][0], v[0], v[1]); upk2(acc[r][1], v[2], v[3]);
        upk2(acc[r][2], v[4], v[5]); upk2(acc[r][3], v[6], v[7]);
        size_t base = (size_t)(row0 + rg * 4 + r) * 512 + gt * 128 + j0;
        *(float4*)&outp[base] = make_float4(v[0] + bs[0], v[1] + bs[1], v[2] + bs[2], v[3] + bs[3]);
        *(float4*)&outp[base + 4] = make_float4(v[4] + bs[4], v[5] + bs[5], v[6] + bs[6], v[7] + bs[7]);
    }
}

// ---- recurrence: 2-CTA cluster, 64 units/CTA, 16 batch rows/cluster ----
#define HSTR 18
#define HBUF (128 * HSTR)
#define REC_SMEM (128 * 256 * 4 + 2 * HBUF * 8)

__global__ void __cluster_dims__(2, 1, 1) __launch_bounds__(256, 1)
k_recur(const float* __restrict__ Whh, const float* __restrict__ xp,
        float* __restrict__ hseq, float* __restrict__ hlast, int store_all)
{
    extern __shared__ float sm[];
    float* Wsm = sm;                        // [128][256] = u*4+q per k
    ull* hb = (ull*)(sm + 128 * 256);       // [2][128][HSTR] (h,h) pairs

    const int tid = threadIdx.x;
    const int rank = blockIdx.x & 1, peer = rank ^ 1, cl = blockIdx.x >> 1;
    const int u_l = tid >> 2, bg = tid & 3;
    const int ug = rank * 64 + u_l;
    const int b0 = cl * 16 + bg * 4;

    for (int i = tid; i < 256 * 128; i += 256) {
        int row = i >> 7, k = i & 127;
        Wsm[k * 256 + row] = Whh[(size_t)((row & 3) * 128 + rank * 64 + (row >> 2)) * 128 + k];
    }
    for (int i = tid; i < 2 * HBUF; i += 256) hb[i] = 0ULL;

    uint32_t pbase;
    {
        uint32_t lb = (uint32_t)__cvta_generic_to_shared(hb);
        asm("mapa.shared::cluster.u32 %0,%1,%2;" : "=r"(pbase) : "r"(lb), "r"(peer));
    }
    asm volatile("barrier.cluster.arrive;\n\tbarrier.cluster.wait;" ::: "memory");

    const ulonglong2* wv = (const ulonglong2*)Wsm;   // stride 64 per k
    const ulonglong2* xpv = (const ulonglong2*)xp;

    float c[4] = {0.f, 0.f, 0.f, 0.f};
    ulonglong2 pf[4];
#pragma unroll
    for (int j = 0; j < 4; j++) pf[j] = xpv[(size_t)(b0 + j) * 512 * 128 + ug];

    for (int t = 0; t < 512; ++t) {
        const ull* hr = hb + ((t & 1) ? HBUF : 0);
        ull* hw = hb + ((t & 1) ? 0 : HBUF);
        const uint32_t pw = pbase + ((t & 1) ? 0 : HBUF * 8);

        ull aif[4], ago[4];
#pragma unroll
        for (int j = 0; j < 4; j++) { aif[j] = pf[j].x; ago[j] = pf[j].y; }
        if (t + 1 < 512) {
#pragma unroll
            for (int j = 0; j < 4; j++)
                pf[j] = xpv[((size_t)(b0 + j) * 512 + t + 1) * 128 + ug];
        }

#pragma unroll 4
        for (int k = 0; k < 128; ++k) {
            ulonglong2 w = wv[k * 64 + u_l];
            ulonglong2 hA = *(const ulonglong2*)&hr[k * HSTR + bg * 4];
            ulonglong2 hB = *(const ulonglong2*)&hr[k * HSTR + bg * 4 + 2];
            fma2(aif[0], w.x, hA.x); fma2(ago[0], w.y, hA.x);
            fma2(aif[1], w.x, hA.y); fma2(ago[1], w.y, hA.y);
            fma2(aif[2], w.x, hB.x); fma2(ago[2], w.y, hB.x);
            fma2(aif[3], w.x, hB.y); fma2(ago[3], w.y, hB.y);
        }

        float hv[4];
#pragma unroll
        for (int j = 0; j < 4; j++) {
            float gi, gf, gc, go;
            upk2(aif[j], gi, gf); upk2(ago[j], gc, go);
            float ii = sigf(gi), ff = sigf(gf), gz = tanhf_(gc), oo = sigf(go);
            c[j] = ff * c[j] + ii * gz;
            hv[j] = oo * tanhf_(c[j]);
        }

        const int idx = ug * HSTR + bg * 4;
#pragma unroll
        for (int j = 0; j < 4; j++) {
            ull p = pk2(hv[j], hv[j]);
            hw[idx + j] = p;
            asm volatile("st.shared::cluster.u64 [%0],%1;" :: "r"(pw + (idx + j) * 8), "l"(p) : "memory");
        }

        if (store_all) {
#pragma unroll
            for (int j = 0; j < 4; j++)
                hseq[((size_t)(b0 + j) * 512 + t) * 128 + ug] = hv[j];
        } else if (t == 511) {
#pragma unroll
            for (int j = 0; j < 4; j++)
                hlast[(size_t)(b0 + j) * 128 + ug] = hv[j];
        }
        asm volatile("barrier.cluster.arrive;\n\tbarrier.cluster.wait;" ::: "memory");
    }
}

// ---- head MLP ----
__global__ void __launch_bounds__(128)
k_head(const float* __restrict__ h2, const float* __restrict__ f1w,
       const float* __restrict__ f1b, const float* __restrict__ f2w,
       const float* __restrict__ f2b, float* __restrict__ out)
{
    __shared__ float w1[64 * 128], w2[64], b1[64];
    const int tid = threadIdx.x;
    for (int i = tid; i < 64 * 128; i += 128) w1[i] = f1w[i];
    if (tid < 64) { w2[tid] = f2w[tid]; b1[tid] = f1b[tid]; }
    __syncthreads();
    const int b = blockIdx.x * 128 + tid;
    float hreg[128];
#pragma unroll
    for (int k = 0; k < 128; k++) hreg[k] = h2[(size_t)b * 128 + k];
    float acc = f2b[0];
    for (int j = 0; j < 64; j++) {
        float a = b1[j];
#pragma unroll
        for (int k = 0; k < 128; k++) a = fmaf(w1[j * 128 + k], hreg[k], a);
        acc = fmaf(w2[j], fmaxf(a, 0.f), acc);
    }
    out[b] = acc;
}

extern "C" void kernel_launch(void* const* d_in, const int* in_sizes, int n_in,
                              void* d_out, int out_size)
{
    const float* x = (const float*)d_in[0];
    const float* Wih0 = (const float*)d_in[1];
    const float* Whh0 = (const float*)d_in[2];
    const float* bih0 = (const float*)d_in[3];
    const float* bhh0 = (const float*)d_in[4];
    const float* Wih1 = (const float*)d_in[5];
    const float* Whh1 = (const float*)d_in[6];
    const float* bih1 = (const float*)d_in[7];
    const float* bhh1 = (const float*)d_in[8];
    const float* f1w = (const float*)d_in[9];
    const float* f1b = (const float*)d_in[10];
    const float* f2w = (const float*)d_in[11];
    const float* f2b = (const float*)d_in[12];
    float* out = (float*)d_out;

    float *xp, *h1, *h2;
    cudaGetSymbolAddress((void**)&xp, g_xp);
    cudaGetSymbolAddress((void**)&h1, g_h1);
    cudaGetSymbolAddress((void**)&h2, g_h2);

    const int smA = (64 * 68 + 64 * 132) * 4;
    const int smC = (128 * 68 + 128 * 132) * 4;
    cudaFuncSetAttribute((const void*)k_xproj<64>, cudaFuncAttributeMaxDynamicSharedMemorySize, smA);
    cudaFuncSetAttribute((const void*)k_xproj<128>, cudaFuncAttributeMaxDynamicSharedMemorySize, smC);
    cudaFuncSetAttribute((const void*)k_recur, cudaFuncAttributeMaxDynamicSharedMemorySize, REC_SMEM);

    dim3 gA(8192, 4);
    k_xproj<64><<<gA, 256, smA>>>(x, Wih0, bih0, bhh0, xp);
    k_recur<<<128, 256, REC_SMEM>>>(Whh0, xp, h1, h2, 1);
    k_xproj<128><<<gA, 256, smC>>>(h1, Wih1, bih1, bhh1, xp);
    k_recur<<<128, 256, REC_SMEM>>>(Whh1, xp, h1, h2, 0);
    k_head<<<8, 128>>>(h2, f1w, f1b, f2w, f2b, out);
}